// round 1
// baseline (speedup 1.0000x reference)
#include <cuda_runtime.h>
#include <cuda_fp16.h>
#include <mma.h>

using namespace nvcuda;

#define NPTS 65536
#define DIN 256
#define DOUT 256
#define NHEAD 8
#define DH 32
#define NTRK 256
#define LSEQ 256

// Scratch (device globals -- no allocations allowed in kernel_launch)
__device__ __half g_valh[(size_t)NPTS * DIN];            // values in fp16
__device__ __half g_wqkvh[3 * DOUT * DIN];               // w_qkv fp16 (row-major [768,256] == col-major W^T)
__device__ __half g_wlinh[DOUT * DIN];                   // w_lin fp16
__device__ __half g_qkvh[(size_t)NPTS * 3 * DOUT];       // qkv activations fp16 [N, 768]
__device__ __half g_ctxh[(size_t)NPTS * DOUT];           // attention context fp16 [N, 256]

// ---------------------------------------------------------------------------
// fp32 -> fp16 convert (vectorized)
// ---------------------------------------------------------------------------
__global__ void f2h_kernel(const float* __restrict__ in, __half* __restrict__ out, int n4) {
    int i = blockIdx.x * blockDim.x + threadIdx.x;
    if (i < n4) {
        float4 v = reinterpret_cast<const float4*>(in)[i];
        reinterpret_cast<__half2*>(out)[2 * i]     = __floats2half2_rn(v.x, v.y);
        reinterpret_cast<__half2*>(out)[2 * i + 1] = __floats2half2_rn(v.z, v.w);
    }
}

// ---------------------------------------------------------------------------
// GEMM: C[M,Nc] = A[M,K] @ W^T + bias,  W is [Nc,K] row-major (= B col-major).
// fp16 inputs, fp32 accumulate. Block tile 128x64, BK=32, 8 warps (32x32 each).
// ---------------------------------------------------------------------------
template <bool OUT_HALF>
__global__ __launch_bounds__(256) void gemm_bias_kernel(
    const __half* __restrict__ A, const __half* __restrict__ W,
    const float* __restrict__ bias, void* __restrict__ Cout,
    int M, int Nc, int K)
{
    constexpr int BM = 128, BN = 64, BK = 32, LDT = BK + 8, LDC = 36;
    // union: tile phase uses 15360 B, epilogue staging uses 36864 B
    __shared__ __align__(16) unsigned char smembuf[8 * 32 * LDC * 4];
    __half (*As)[LDT] = reinterpret_cast<__half(*)[LDT]>(smembuf);
    __half (*Bs)[LDT] = reinterpret_cast<__half(*)[LDT]>(smembuf + BM * LDT * 2);

    const int tid = threadIdx.x;
    const int lane = tid & 31, warp = tid >> 5;
    const int wr = warp & 3, wc = warp >> 2;          // warp grid 4x2
    const int rowBase = blockIdx.y * BM;
    const int colBase = blockIdx.x * BN;

    wmma::fragment<wmma::accumulator, 16, 16, 16, float> acc[2][2];
#pragma unroll
    for (int i = 0; i < 2; i++)
#pragma unroll
        for (int j = 0; j < 2; j++) wmma::fill_fragment(acc[i][j], 0.0f);

    for (int kb = 0; kb < K; kb += BK) {
        // load A tile: 128 rows x 32 halves = 512 uint4, 2 per thread
#pragma unroll
        for (int it = 0; it < 2; it++) {
            int idx = tid + it * 256;
            int r = idx >> 2, q = idx & 3;
            *reinterpret_cast<uint4*>(&As[r][q * 8]) =
                *reinterpret_cast<const uint4*>(A + (size_t)(rowBase + r) * K + kb + q * 8);
        }
        // load B tile: 64 "cols" x 32 halves = 256 uint4, 1 per thread
        {
            int j = tid >> 2, q = tid & 3;
            *reinterpret_cast<uint4*>(&Bs[j][q * 8]) =
                *reinterpret_cast<const uint4*>(W + (size_t)(colBase + j) * K + kb + q * 8);
        }
        __syncthreads();

#pragma unroll
        for (int kk = 0; kk < BK; kk += 16) {
            wmma::fragment<wmma::matrix_a, 16, 16, 16, __half, wmma::row_major> a0, a1;
            wmma::load_matrix_sync(a0, &As[wr * 32][kk], LDT);
            wmma::load_matrix_sync(a1, &As[wr * 32 + 16][kk], LDT);
            wmma::fragment<wmma::matrix_b, 16, 16, 16, __half, wmma::col_major> b0, b1;
            wmma::load_matrix_sync(b0, &Bs[wc * 32][kk], LDT);
            wmma::load_matrix_sync(b1, &Bs[wc * 32 + 16][kk], LDT);
            wmma::mma_sync(acc[0][0], a0, b0, acc[0][0]);
            wmma::mma_sync(acc[0][1], a0, b1, acc[0][1]);
            wmma::mma_sync(acc[1][0], a1, b0, acc[1][0]);
            wmma::mma_sync(acc[1][1], a1, b1, acc[1][1]);
        }
        __syncthreads();
    }

    // epilogue: stage fp32 accum through smem, add bias, store
    float* Cw = reinterpret_cast<float*>(smembuf) + warp * (32 * LDC);
    wmma::store_matrix_sync(Cw, acc[0][0], LDC, wmma::mem_row_major);
    wmma::store_matrix_sync(Cw + 16, acc[0][1], LDC, wmma::mem_row_major);
    wmma::store_matrix_sync(Cw + 16 * LDC, acc[1][0], LDC, wmma::mem_row_major);
    wmma::store_matrix_sync(Cw + 16 * LDC + 16, acc[1][1], LDC, wmma::mem_row_major);
    __syncwarp();

    const int gr = rowBase + wr * 32 + lane;
    const int gc = colBase + wc * 32;
    const float* cr = Cw + lane * LDC;
    if (OUT_HALF) {
        __half* dst = reinterpret_cast<__half*>(Cout) + (size_t)gr * Nc + gc;
#pragma unroll
        for (int c = 0; c < 32; c += 2) {
            float v0 = cr[c] + bias[gc + c];
            float v1 = cr[c + 1] + bias[gc + c + 1];
            *reinterpret_cast<__half2*>(dst + c) = __floats2half2_rn(v0, v1);
        }
    } else {
        float* dst = reinterpret_cast<float*>(Cout) + (size_t)gr * Nc + gc;
#pragma unroll
        for (int c = 0; c < 32; c++) {
            dst[c] = cr[c] + bias[gc + c];
        }
    }
}

// ---------------------------------------------------------------------------
// Attention: one block per (track, head). K/V resident in smem; 64-row Q
// chunks; fp32 scores + fp32 softmax; P@V via wmma; context stored fp16.
// ---------------------------------------------------------------------------
__global__ __launch_bounds__(256) void attn_kernel(const __half* __restrict__ qkv,
                                                   __half* __restrict__ ctxout)
{
    constexpr int LDK = 40;   // half rows (K/V/Q tiles)
    constexpr int LDS = 264;  // fp32 score rows & half prob rows
    extern __shared__ __align__(16) unsigned char sm[];
    __half* Ksm = reinterpret_cast<__half*>(sm);                   // 256*40 h = 20480 B
    __half* Vsm = Ksm + 256 * LDK;                                 // 20480 B
    __half* Qsm = Vsm + 256 * LDK;                                 // 64*40 h = 5120 B
    float*  Ssm = reinterpret_cast<float*>(sm + 46080);            // 64*264 f = 67584 B
    __half* Psm = reinterpret_cast<__half*>(sm + 113664);          // 64*264 h = 33792 B
                                                                   // total 147456 B
    const int tid = threadIdx.x, lane = tid & 31, warp = tid >> 5;
    const int t = blockIdx.x >> 3, h = blockIdx.x & 7;
    const float scale = 0.17677669529663687f;  // 1/sqrt(32)

    // Load K, V tiles (row per thread, 4x uint4 each)
    {
        const int m = tid;
        const uint4* ks = reinterpret_cast<const uint4*>(qkv + (size_t)(t * LSEQ + m) * 768 + 256 + h * DH);
        const uint4* vs = reinterpret_cast<const uint4*>(qkv + (size_t)(t * LSEQ + m) * 768 + 512 + h * DH);
        uint4* kd = reinterpret_cast<uint4*>(Ksm + m * LDK);
        uint4* vd = reinterpret_cast<uint4*>(Vsm + m * LDK);
#pragma unroll
        for (int q = 0; q < 4; q++) { kd[q] = ks[q]; vd[q] = vs[q]; }
    }
    __syncthreads();

    for (int c0 = 0; c0 < LSEQ; c0 += 64) {
        // Load Q chunk (64 x 32)
        {
            int r = tid >> 2, q = tid & 3;
            const uint4* qs = reinterpret_cast<const uint4*>(qkv + (size_t)(t * LSEQ + c0 + r) * 768 + h * DH);
            reinterpret_cast<uint4*>(Qsm + r * LDK)[q] = qs[q];
        }
        __syncthreads();

        // S = Q K^T * scale   (64 x 256, fp32). Warp tile: 16 rows x 128 cols.
        {
            const int r0 = (warp & 3) * 16, cb = (warp >> 2) * 128;
            wmma::fragment<wmma::accumulator, 16, 16, 16, float> acc[8];
#pragma unroll
            for (int j = 0; j < 8; j++) wmma::fill_fragment(acc[j], 0.0f);
#pragma unroll
            for (int kk = 0; kk < 32; kk += 16) {
                wmma::fragment<wmma::matrix_a, 16, 16, 16, __half, wmma::row_major> af;
                wmma::load_matrix_sync(af, Qsm + r0 * LDK + kk, LDK);
#pragma unroll
                for (int j = 0; j < 8; j++) {
                    wmma::fragment<wmma::matrix_b, 16, 16, 16, __half, wmma::col_major> bf;
                    wmma::load_matrix_sync(bf, Ksm + (cb + j * 16) * LDK + kk, LDK);
                    wmma::mma_sync(acc[j], af, bf, acc[j]);
                }
            }
#pragma unroll
            for (int j = 0; j < 8; j++) {
#pragma unroll
                for (int e = 0; e < acc[j].num_elements; e++) acc[j].x[e] *= scale;
                wmma::store_matrix_sync(Ssm + r0 * LDS + cb + j * 16, acc[j], LDS, wmma::mem_row_major);
            }
        }
        __syncthreads();

        // Softmax in fp32; probs to fp16. 8 rows per warp.
        {
#pragma unroll
            for (int i = 0; i < 8; i++) {
                const int r = warp * 8 + i;
                const float* srow = Ssm + r * LDS;
                float v[8];
                float mx = -1e30f;
#pragma unroll
                for (int q = 0; q < 8; q++) { v[q] = srow[lane + q * 32]; mx = fmaxf(mx, v[q]); }
#pragma unroll
                for (int o = 16; o > 0; o >>= 1) mx = fmaxf(mx, __shfl_xor_sync(0xffffffffu, mx, o));
                float s = 0.0f;
#pragma unroll
                for (int q = 0; q < 8; q++) { v[q] = __expf(v[q] - mx); s += v[q]; }
#pragma unroll
                for (int o = 16; o > 0; o >>= 1) s += __shfl_xor_sync(0xffffffffu, s, o);
                const float inv = 1.0f / s;
                __half* prow = Psm + r * LDS;
#pragma unroll
                for (int q = 0; q < 8; q++) prow[lane + q * 32] = __float2half_rn(v[q] * inv);
            }
        }
        __syncthreads();

        // ctx = P @ V  (64 x 32). Warp tile 16x16, 8 warps cover 4x2 tiles.
        {
            const int r0 = (warp >> 1) * 16, cc = (warp & 1) * 16;
            wmma::fragment<wmma::accumulator, 16, 16, 16, float> acc;
            wmma::fill_fragment(acc, 0.0f);
#pragma unroll
            for (int kk = 0; kk < 256; kk += 16) {
                wmma::fragment<wmma::matrix_a, 16, 16, 16, __half, wmma::row_major> af;
                wmma::load_matrix_sync(af, Psm + r0 * LDS + kk, LDS);
                wmma::fragment<wmma::matrix_b, 16, 16, 16, __half, wmma::row_major> bf;
                wmma::load_matrix_sync(bf, Vsm + kk * LDK + cc, LDK);
                wmma::mma_sync(acc, af, bf, acc);
            }
            wmma::store_matrix_sync(Ssm + r0 * LDS + cc, acc, LDS, wmma::mem_row_major);
        }
        __syncthreads();

        // write ctx chunk (fp16), rows 0..63, cols h*32..h*32+31
        if (tid < 64) {
            const int n = t * LSEQ + c0 + tid;
            const float* srow = Ssm + tid * LDS;
            __half* dst = ctxout + (size_t)n * DOUT + h * DH;
#pragma unroll
            for (int c = 0; c < 32; c += 2)
                *reinterpret_cast<__half2*>(dst + c) = __floats2half2_rn(srow[c], srow[c + 1]);
        }
        __syncthreads();
    }
}

// ---------------------------------------------------------------------------
extern "C" void kernel_launch(void* const* d_in, const int* in_sizes, int n_in,
                              void* d_out, int out_size)
{
    const float* values = (const float*)d_in[0];
    const float* wqkv   = (const float*)d_in[1];
    const float* bqkv   = (const float*)d_in[2];
    const float* wlin   = (const float*)d_in[3];
    const float* blin   = (const float*)d_in[4];
    // d_in[5] = track_ids (sorted, equal-length tracks -> identity layout; unused)

    void *p_valh, *p_wqkvh, *p_wlinh, *p_qkvh, *p_ctxh;
    cudaGetSymbolAddress(&p_valh, g_valh);
    cudaGetSymbolAddress(&p_wqkvh, g_wqkvh);
    cudaGetSymbolAddress(&p_wlinh, g_wlinh);
    cudaGetSymbolAddress(&p_qkvh, g_qkvh);
    cudaGetSymbolAddress(&p_ctxh, g_ctxh);

    cudaFuncSetAttribute(attn_kernel, cudaFuncAttributeMaxDynamicSharedMemorySize, 147456);

    // 1) convert inputs to fp16
    f2h_kernel<<<(NPTS * DIN / 4 + 255) / 256, 256>>>(values, (__half*)p_valh, NPTS * DIN / 4);
    f2h_kernel<<<(3 * DOUT * DIN / 4 + 255) / 256, 256>>>(wqkv, (__half*)p_wqkvh, 3 * DOUT * DIN / 4);
    f2h_kernel<<<(DOUT * DIN / 4 + 255) / 256, 256>>>(wlin, (__half*)p_wlinh, DOUT * DIN / 4);

    // 2) QKV projection: [65536,768] = values @ w_qkv^T + b_qkv  (fp16 out)
    gemm_bias_kernel<true><<<dim3(768 / 64, NPTS / 128), 256>>>(
        (const __half*)p_valh, (const __half*)p_wqkvh, bqkv, p_qkvh, NPTS, 768, 256);

    // 3) per-(track, head) attention -> context fp16 [65536,256]
    attn_kernel<<<NTRK * NHEAD, 256, 147456>>>((const __half*)p_qkvh, (__half*)p_ctxh);

    // 4) output projection: [65536,256] = ctx @ w_lin^T + b_lin  (fp32 out)
    gemm_bias_kernel<false><<<dim3(256 / 64, NPTS / 128), 256>>>(
        (const __half*)p_ctxh, (const __half*)p_wlinh, blin, d_out, NPTS, 256, 256);
}

// round 2
// speedup vs baseline: 1.5374x; 1.5374x over previous
#include <cuda_runtime.h>
#include <cuda_fp16.h>
#include <mma.h>

using namespace nvcuda;

#define NPTS 65536
#define DIN 256
#define DOUT 256
#define NHEAD 8
#define DH 32
#define NTRK 256
#define LSEQ 256

// Scratch (device globals -- no allocations allowed)
__device__ __half g_valh[(size_t)NPTS * DIN];
__device__ __half g_wqkvh[3 * DOUT * DIN];
__device__ __half g_wlinh[DOUT * DIN];
__device__ __half g_qkvh[(size_t)NPTS * 3 * DOUT];
__device__ __half g_ctxh[(size_t)NPTS * DOUT];

// ---------------------------------------------------------------------------
__device__ __forceinline__ void cp_async16(void* smem, const void* gmem) {
    unsigned s = (unsigned)__cvta_generic_to_shared(smem);
    asm volatile("cp.async.cg.shared.global [%0], [%1], 16;\n" :: "r"(s), "l"(gmem));
}
__device__ __forceinline__ void cp_commit() { asm volatile("cp.async.commit_group;\n"); }
template <int N> __device__ __forceinline__ void cp_wait() {
    asm volatile("cp.async.wait_group %0;\n" :: "n"(N));
}

// ---------------------------------------------------------------------------
// fp32 -> fp16 convert
// ---------------------------------------------------------------------------
__global__ void f2h_kernel(const float* __restrict__ in, __half* __restrict__ out, int n4) {
    int i = blockIdx.x * blockDim.x + threadIdx.x;
    if (i < n4) {
        float4 v = reinterpret_cast<const float4*>(in)[i];
        reinterpret_cast<__half2*>(out)[2 * i]     = __floats2half2_rn(v.x, v.y);
        reinterpret_cast<__half2*>(out)[2 * i + 1] = __floats2half2_rn(v.z, v.w);
    }
}

// ---------------------------------------------------------------------------
// Pipelined GEMM: C[M,Nc] = A[M,K] @ W^T + bias.  W row-major [Nc,K].
// BM=128 BN=128 BK=64, 2-stage cp.async, 8 warps in 2x4, warp tile 64x32.
// ---------------------------------------------------------------------------
template <bool OUT_HALF>
__global__ __launch_bounds__(256) void gemm_bias_kernel(
    const __half* __restrict__ A, const __half* __restrict__ W,
    const float* __restrict__ bias, void* __restrict__ Cout,
    int M, int Nc, int K)
{
    constexpr int BM = 128, BN = 128, BK = 64, LDT = 72, LDC = 36;
    constexpr int STAGE_B = (BM + BN) * LDT * 2;            // 36864 bytes
    extern __shared__ __align__(16) unsigned char sm[];     // 2*STAGE_B = 73728

    const int tid = threadIdx.x;
    const int lane = tid & 31, warp = tid >> 5;
    const int wr = warp >> 2, wc = warp & 3;                // 2x4 warp grid
    const int rowBase = blockIdx.y * BM;
    const int colBase = blockIdx.x * BN;
    const int NKB = K / BK;

    auto load_stage = [&](int s, int kb) {
        __half* As = reinterpret_cast<__half*>(sm + s * STAGE_B);
        __half* Bs = As + BM * LDT;
        const __half* Ag = A + (size_t)rowBase * K + kb * BK;
        const __half* Wg = W + (size_t)colBase * K + kb * BK;
#pragma unroll
        for (int i = 0; i < 4; i++) {
            int idx = tid + i * 256;
            int r = idx >> 3, c = idx & 7;
            cp_async16(As + r * LDT + c * 8, Ag + (size_t)r * K + c * 8);
        }
#pragma unroll
        for (int i = 0; i < 4; i++) {
            int idx = tid + i * 256;
            int r = idx >> 3, c = idx & 7;
            cp_async16(Bs + r * LDT + c * 8, Wg + (size_t)r * K + c * 8);
        }
    };

    wmma::fragment<wmma::accumulator, 16, 16, 16, float> acc[4][2];
#pragma unroll
    for (int i = 0; i < 4; i++)
#pragma unroll
        for (int j = 0; j < 2; j++) wmma::fill_fragment(acc[i][j], 0.0f);

    load_stage(0, 0);
    cp_commit();

    for (int kb = 0; kb < NKB; kb++) {
        if (kb + 1 < NKB) load_stage((kb + 1) & 1, kb + 1);
        cp_commit();
        cp_wait<1>();
        __syncthreads();

        const __half* As = reinterpret_cast<const __half*>(sm + (kb & 1) * STAGE_B);
        const __half* Bs = As + BM * LDT;
#pragma unroll
        for (int kk = 0; kk < BK; kk += 16) {
            wmma::fragment<wmma::matrix_a, 16, 16, 16, __half, wmma::row_major> af[4];
#pragma unroll
            for (int i = 0; i < 4; i++)
                wmma::load_matrix_sync(af[i], As + (wr * 64 + i * 16) * LDT + kk, LDT);
#pragma unroll
            for (int j = 0; j < 2; j++) {
                wmma::fragment<wmma::matrix_b, 16, 16, 16, __half, wmma::col_major> bf;
                wmma::load_matrix_sync(bf, Bs + (wc * 32 + j * 16) * LDT + kk, LDT);
#pragma unroll
                for (int i = 0; i < 4; i++)
                    wmma::mma_sync(acc[i][j], af[i], bf, acc[i][j]);
            }
        }
        __syncthreads();
    }

    // epilogue via smem staging (64x36 fp32 per warp = exactly 73728 total)
    float* Cw = reinterpret_cast<float*>(sm) + warp * (64 * LDC);
#pragma unroll
    for (int i = 0; i < 4; i++)
#pragma unroll
        for (int j = 0; j < 2; j++)
            wmma::store_matrix_sync(Cw + i * 16 * LDC + j * 16, acc[i][j], LDC, wmma::mem_row_major);
    __syncwarp();

    const int gc = colBase + wc * 32;
#pragma unroll
    for (int rr = 0; rr < 2; rr++) {
        const int row = lane + rr * 32;
        const int gr = rowBase + wr * 64 + row;
        const float* cr = Cw + row * LDC;
        if (OUT_HALF) {
            __half* dst = reinterpret_cast<__half*>(Cout) + (size_t)gr * Nc + gc;
#pragma unroll
            for (int c = 0; c < 32; c += 2)
                *reinterpret_cast<__half2*>(dst + c) =
                    __floats2half2_rn(cr[c] + bias[gc + c], cr[c + 1] + bias[gc + c + 1]);
        } else {
            float* dst = reinterpret_cast<float*>(Cout) + (size_t)gr * Nc + gc;
#pragma unroll
            for (int c = 0; c < 32; c++) dst[c] = cr[c] + bias[gc + c];
        }
    }
}

// ---------------------------------------------------------------------------
// Attention: one block per (track, head). Softmax on accumulator fragments in
// registers (sm_80+ m16n8k16 layout); unnormalized fp16 probs -> PV -> scale.
// smem: K 20480 + V 20480 + Q 5120 + P 33792 + red 1024 = 80896 B (2 CTA/SM).
// ---------------------------------------------------------------------------
__global__ __launch_bounds__(256) void attn_kernel(const __half* __restrict__ qkv,
                                                   __half* __restrict__ ctxout)
{
    constexpr int LDK = 40, LDP = 264;
    extern __shared__ __align__(16) unsigned char sm[];
    __half* Ksm = reinterpret_cast<__half*>(sm);                    // 20480
    __half* Vsm = Ksm + 256 * LDK;                                  // 20480
    __half* Qsm = Vsm + 256 * LDK;                                  // 5120
    __half* Psm = Qsm + 64 * LDK;                                   // 33792
    float*  redM = reinterpret_cast<float*>(sm + 79872);            // [2][64]
    float*  redS = redM + 128;                                      // [2][64]

    const int tid = threadIdx.x, lane = tid & 31, warp = tid >> 5;
    const int g = lane >> 2, t4 = lane & 3;
    const int t = blockIdx.x >> 3, h = blockIdx.x & 7;
    const float scale = 0.17677669529663687f;  // 1/sqrt(32)

    // K,V resident (one row per thread)
    {
        const uint4* ks = reinterpret_cast<const uint4*>(qkv + (size_t)(t * LSEQ + tid) * 768 + 256 + h * DH);
        const uint4* vs = reinterpret_cast<const uint4*>(qkv + (size_t)(t * LSEQ + tid) * 768 + 512 + h * DH);
        uint4* kd = reinterpret_cast<uint4*>(Ksm + tid * LDK);
        uint4* vd = reinterpret_cast<uint4*>(Vsm + tid * LDK);
#pragma unroll
        for (int q = 0; q < 4; q++) { kd[q] = ks[q]; vd[q] = vs[q]; }
    }

    for (int c0 = 0; c0 < LSEQ; c0 += 64) {
        // Q chunk: 64 x 32
        {
            int r = tid >> 2, q = tid & 3;
            const uint4* qs = reinterpret_cast<const uint4*>(qkv + (size_t)(t * LSEQ + c0 + r) * 768 + h * DH);
            reinterpret_cast<uint4*>(Qsm + r * LDK)[q] = qs[q];
        }
        __syncthreads();

        // S = Q K^T: warp (wr=w&3 rows, ch=w>>2 col half of 128)
        const int wr = warp & 3, ch = warp >> 2;
        const int r0 = wr * 16, cb = ch * 128;
        wmma::fragment<wmma::accumulator, 16, 16, 16, float> S[8];
#pragma unroll
        for (int j = 0; j < 8; j++) wmma::fill_fragment(S[j], 0.0f);
#pragma unroll
        for (int kk = 0; kk < 32; kk += 16) {
            wmma::fragment<wmma::matrix_a, 16, 16, 16, __half, wmma::row_major> af;
            wmma::load_matrix_sync(af, Qsm + r0 * LDK + kk, LDK);
#pragma unroll
            for (int j = 0; j < 8; j++) {
                wmma::fragment<wmma::matrix_b, 16, 16, 16, __half, wmma::col_major> bf;
                wmma::load_matrix_sync(bf, Ksm + (cb + j * 16) * LDK + kk, LDK);
                wmma::mma_sync(S[j], af, bf, S[j]);
            }
        }

        // row max (rows r0+g and r0+g+8) across this warp's 128 cols
        float mx0 = -1e30f, mx1 = -1e30f;
#pragma unroll
        for (int j = 0; j < 8; j++) {
            mx0 = fmaxf(mx0, fmaxf(fmaxf(S[j].x[0], S[j].x[1]), fmaxf(S[j].x[4], S[j].x[5])));
            mx1 = fmaxf(mx1, fmaxf(fmaxf(S[j].x[2], S[j].x[3]), fmaxf(S[j].x[6], S[j].x[7])));
        }
#pragma unroll
        for (int o = 1; o <= 2; o <<= 1) {
            mx0 = fmaxf(mx0, __shfl_xor_sync(0xffffffffu, mx0, o));
            mx1 = fmaxf(mx1, __shfl_xor_sync(0xffffffffu, mx1, o));
        }
        if (t4 == 0) { redM[ch * 64 + r0 + g] = mx0; redM[ch * 64 + r0 + 8 + g] = mx1; }
        __syncthreads();

        const float gm0 = fmaxf(redM[r0 + g], redM[64 + r0 + g]);
        const float gm1 = fmaxf(redM[r0 + 8 + g], redM[64 + r0 + 8 + g]);

        // exp (unnormalized), write fp16 probs, accumulate row sums
        float sm0 = 0.0f, sm1 = 0.0f;
#pragma unroll
        for (int j = 0; j < 8; j++) {
            float e0 = __expf((S[j].x[0] - gm0) * scale);
            float e1 = __expf((S[j].x[1] - gm0) * scale);
            float e2 = __expf((S[j].x[2] - gm1) * scale);
            float e3 = __expf((S[j].x[3] - gm1) * scale);
            float e4 = __expf((S[j].x[4] - gm0) * scale);
            float e5 = __expf((S[j].x[5] - gm0) * scale);
            float e6 = __expf((S[j].x[6] - gm1) * scale);
            float e7 = __expf((S[j].x[7] - gm1) * scale);
            sm0 += e0 + e1 + e4 + e5;
            sm1 += e2 + e3 + e6 + e7;
            __half2* p0 = reinterpret_cast<__half2*>(Psm + (r0 + g) * LDP + cb + j * 16 + 2 * t4);
            __half2* p1 = reinterpret_cast<__half2*>(Psm + (r0 + 8 + g) * LDP + cb + j * 16 + 2 * t4);
            p0[0] = __floats2half2_rn(e0, e1);
            p0[4] = __floats2half2_rn(e4, e5);
            p1[0] = __floats2half2_rn(e2, e3);
            p1[4] = __floats2half2_rn(e6, e7);
        }
#pragma unroll
        for (int o = 1; o <= 2; o <<= 1) {
            sm0 += __shfl_xor_sync(0xffffffffu, sm0, o);
            sm1 += __shfl_xor_sync(0xffffffffu, sm1, o);
        }
        if (t4 == 0) { redS[ch * 64 + r0 + g] = sm0; redS[ch * 64 + r0 + 8 + g] = sm1; }
        __syncthreads();

        // ctx = P @ V  (64x32), warp grid 4x2: 16x16 tiles
        {
            const int rp = (warp >> 1) * 16, cc = (warp & 1) * 16;
            wmma::fragment<wmma::accumulator, 16, 16, 16, float> O;
            wmma::fill_fragment(O, 0.0f);
#pragma unroll
            for (int kk = 0; kk < 256; kk += 16) {
                wmma::fragment<wmma::matrix_a, 16, 16, 16, __half, wmma::row_major> af;
                wmma::load_matrix_sync(af, Psm + rp * LDP + kk, LDP);
                wmma::fragment<wmma::matrix_b, 16, 16, 16, __half, wmma::row_major> bf;
                wmma::load_matrix_sync(bf, Vsm + kk * LDK + cc, LDK);
                wmma::mma_sync(O, af, bf, O);
            }
            const float inv0 = 1.0f / (redS[rp + g] + redS[64 + rp + g]);
            const float inv1 = 1.0f / (redS[rp + 8 + g] + redS[64 + rp + 8 + g]);
            __half* d0 = ctxout + (size_t)(t * LSEQ + c0 + rp + g) * DOUT + h * DH + cc + 2 * t4;
            __half* d1 = ctxout + (size_t)(t * LSEQ + c0 + rp + 8 + g) * DOUT + h * DH + cc + 2 * t4;
            *reinterpret_cast<__half2*>(d0)     = __floats2half2_rn(O.x[0] * inv0, O.x[1] * inv0);
            *reinterpret_cast<__half2*>(d0 + 8) = __floats2half2_rn(O.x[4] * inv0, O.x[5] * inv0);
            *reinterpret_cast<__half2*>(d1)     = __floats2half2_rn(O.x[2] * inv1, O.x[3] * inv1);
            *reinterpret_cast<__half2*>(d1 + 8) = __floats2half2_rn(O.x[6] * inv1, O.x[7] * inv1);
        }
        __syncthreads();
    }
}

// ---------------------------------------------------------------------------
extern "C" void kernel_launch(void* const* d_in, const int* in_sizes, int n_in,
                              void* d_out, int out_size)
{
    const float* values = (const float*)d_in[0];
    const float* wqkv   = (const float*)d_in[1];
    const float* bqkv   = (const float*)d_in[2];
    const float* wlin   = (const float*)d_in[3];
    const float* blin   = (const float*)d_in[4];

    void *p_valh, *p_wqkvh, *p_wlinh, *p_qkvh, *p_ctxh;
    cudaGetSymbolAddress(&p_valh, g_valh);
    cudaGetSymbolAddress(&p_wqkvh, g_wqkvh);
    cudaGetSymbolAddress(&p_wlinh, g_wlinh);
    cudaGetSymbolAddress(&p_qkvh, g_qkvh);
    cudaGetSymbolAddress(&p_ctxh, g_ctxh);

    cudaFuncSetAttribute(gemm_bias_kernel<true>,  cudaFuncAttributeMaxDynamicSharedMemorySize, 73728);
    cudaFuncSetAttribute(gemm_bias_kernel<false>, cudaFuncAttributeMaxDynamicSharedMemorySize, 73728);
    cudaFuncSetAttribute(attn_kernel, cudaFuncAttributeMaxDynamicSharedMemorySize, 80896);

    f2h_kernel<<<(NPTS * DIN / 4 + 255) / 256, 256>>>(values, (__half*)p_valh, NPTS * DIN / 4);
    f2h_kernel<<<(3 * DOUT * DIN / 4 + 255) / 256, 256>>>(wqkv, (__half*)p_wqkvh, 3 * DOUT * DIN / 4);
    f2h_kernel<<<(DOUT * DIN / 4 + 255) / 256, 256>>>(wlin, (__half*)p_wlinh, DOUT * DIN / 4);

    gemm_bias_kernel<true><<<dim3(768 / 128, NPTS / 128), 256, 73728>>>(
        (const __half*)p_valh, (const __half*)p_wqkvh, bqkv, p_qkvh, NPTS, 768, 256);

    attn_kernel<<<NTRK * NHEAD, 256, 80896>>>((const __half*)p_qkvh, (__half*)p_ctxh);

    gemm_bias_kernel<false><<<dim3(256 / 128, NPTS / 128), 256, 73728>>>(
        (const __half*)p_ctxh, (const __half*)p_wlinh, blin, d_out, NPTS, 256, 256);
}